// round 16
// baseline (speedup 1.0000x reference)
#include <cuda_runtime.h>
#include <cuda_fp16.h>
#include <math.h>
#include <stdint.h>

#define Lh    64
#define Dh    16
#define Hh    128
#define ROWS  16
#define THREADS 256
#define CTAS  256
#define HEAD_IN 144
#define OUTD  60

typedef unsigned long long ull;

// ---- SMEM layout (bytes). A images: 16 rows x 264 fp16 (stride 528B). HT: stride 272B.
#define OFF_A0    0
#define OFF_A1    8448
#define OFF_HT    16896
#define OFF_SV    21248
#define OFF_WP    29440
#define OFF_HISTB 37632
#define OFF_MSK   38656
#define OFF_DEC   38720
#define OFF_LAST  38784
#define OFF_BX    38848
#define OFF_BD    41920
#define OFF_WT    42944
#define OFF_BT    43968
#define OFF_BP    44992
#define SMEM_TOTAL 45568
#define F(off) ((off) >> 2)
#define ASTR 528
#define HSTR 272

// layer strides in ulls (fixed in R15: these were wrong in R14)
#define GB_LSTRIDE 24576   // 16*24*32*2
#define WB_LSTRIDE 4096    // 8*8*32*2

// weight blobs, fp16, n-tile PAIRS adjacent per lane for LDG.128 (R12 layout):
// gates: [l][kt(16)][gi(3)*8 + wk(8)][lane(32)][pair(2)] 8B each
__device__ ull g_gb[2*16*24*32*2];
// Wd: [l][kt(8)][wk(8)][lane(32)][pair(2)]
__device__ ull g_wb[2*8*8*32*2];

__global__ void pack_kernel(const float* __restrict__ Wx,
                            const float* __restrict__ Uh,
                            const float* __restrict__ Wd)
{
    int idx = blockIdx.x * blockDim.x + threadIdx.x;   // one ull each
    if (idx < 49152) {
        int pr   = idx & 1;
        int lane = (idx >> 1) & 31;
        int q    = idx >> 6;
        int gw   = q % 24; q /= 24;
        int kt   = q & 15; int l = q >> 4;
        int gate = gw >> 3;
        int wk   = gw & 7;
        int ntile = gate * 16 + wk * 2 + pr;
        int n  = (ntile % 16) * 8 + (lane >> 2);
        int kb = kt * 16 + (lane & 3) * 2;
        ull outv = 0;
        #pragma unroll
        for (int e = 0; e < 4; e++) {
            int kk = kb + (e & 1) + (e >> 1) * 8;   // kb, kb+1, kb+8, kb+9
            float v = (kk < 128)
                ? Wx[((size_t)(l*4 + gate + 1) * 128 + kk) * 128 + n]
                : Uh[((size_t)(l*4 + gate + 1) * 128 + (kk - 128)) * 128 + n];
            __half hv = __float2half_rn(v);
            outv |= (ull)(*(unsigned short*)&hv) << (16 * e);
        }
        g_gb[idx] = outv;
    } else if (idx < 49152 + 8192) {
        int i2   = idx - 49152;
        int pr   = i2 & 1;
        int lane = (i2 >> 1) & 31;
        int q    = i2 >> 6;
        int wk   = q & 7; q >>= 3;
        int kt   = q & 7; int l = q >> 3;
        int ntile = wk * 2 + pr;
        int n  = ntile * 8 + (lane >> 2);
        int kb = kt * 16 + (lane & 3) * 2;
        ull outv = 0;
        #pragma unroll
        for (int e = 0; e < 4; e++) {
            int kk = kb + (e & 1) + (e >> 1) * 8;
            float v = Wd[((size_t)l * 128 + kk) * 128 + n];
            __half hv = __float2half_rn(v);
            outv |= (ull)(*(unsigned short*)&hv) << (16 * e);
        }
        g_wb[i2] = outv;
    }
}

__device__ __forceinline__ uint32_t smem_u32(const void* p) {
    uint32_t a;
    asm("{ .reg .u64 t; cvta.to.shared.u64 t, %1; cvt.u32.u64 %0, t; }" : "=r"(a) : "l"(p));
    return a;
}
__device__ __forceinline__ void ldm4(uint32_t* r, uint32_t addr) {
    asm volatile("ldmatrix.sync.aligned.m8n8.x4.shared.b16 {%0,%1,%2,%3}, [%4];"
        : "=r"(r[0]), "=r"(r[1]), "=r"(r[2]), "=r"(r[3]) : "r"(addr));
}
__device__ __forceinline__ void mma16816(float* c, const uint32_t* a, uint32_t b0, uint32_t b1) {
    asm volatile("mma.sync.aligned.m16n8k16.row.col.f32.f16.f16.f32 "
        "{%0,%1,%2,%3}, {%4,%5,%6,%7}, {%8,%9}, {%0,%1,%2,%3};"
        : "+f"(c[0]), "+f"(c[1]), "+f"(c[2]), "+f"(c[3])
        : "r"(a[0]), "r"(a[1]), "r"(a[2]), "r"(a[3]), "r"(b0), "r"(b1));
}
__device__ __forceinline__ uint32_t packh2(float x, float y) {
    __half2 h = __floats2half2_rn(x, y);
    return *(uint32_t*)&h;
}
__device__ __forceinline__ float tanh_f(float x) {
    float r;
    asm("tanh.approx.f32 %0, %1;" : "=f"(r) : "f"(x));
    return r;
}
__device__ __forceinline__ float sig_f(float x) {
    return fmaf(0.5f, tanh_f(0.5f * x), 0.5f);
}
__device__ __forceinline__ float fixv(float x) {
    if (!(x == x)) return 0.0f;
    if (x > 1e38f) return 1e4f;
    if (x < -1e38f) return -1e4f;
    return x;
}

__global__ void __launch_bounds__(THREADS, 2)
tlstm_mma_kernel(const float* __restrict__ history, const float* __restrict__ hmask,
                 const float* __restrict__ Wp,  const float* __restrict__ bp,
                 const float* __restrict__ bx,  const float* __restrict__ bd,
                 const float* __restrict__ Wt,  const float* __restrict__ bt,
                 const float* __restrict__ ln_g, const float* __restrict__ ln_b,
                 const float* __restrict__ W1,  const float* __restrict__ b1,
                 const float* __restrict__ W2,  const float* __restrict__ b2,
                 float* __restrict__ out)
{
    extern __shared__ char sm[];
    float* smf = (float*)sm;
    int*   lastArr = (int*)(sm + OFF_LAST);
    const uint32_t smb = smem_u32(sm);

    const int tid  = threadIdx.x;
    const int b0   = blockIdx.x * ROWS;
    const int w    = tid >> 5;       // 8 warps: per gate n-tiles {2w, 2w+1}, all 16 rows
    const int lane = tid & 31;
    const int g4   = lane >> 2;
    const int c4   = lane & 3;

    // ldmatrix per-lane byte offsets (single m-tile of 16 rows)
    const int lm_row = (lane & 7) + ((lane >> 3) & 1) * 8;
    const int lm_k8  = ((lane >> 4) & 1) * 8;
    const int lmA = lm_row * ASTR + lm_k8 * 2;
    const int lmH = lm_row * HSTR + lm_k8 * 2;

    // ---- init ----
    for (int i = tid; i < 16896 / 4; i += THREADS)   // zero A0,A1
        ((uint32_t*)sm)[i] = 0;
    for (int i = tid; i < Dh * Hh; i += THREADS)
        smf[F(OFF_WP) + i] = Wp[i];
    for (int i = tid; i < 768; i += THREADS) {       // bx: [l][gate(i,o,c)][k]
        int l = i / 384, gi = (i % 384) / 128, k = i & 127;
        smf[F(OFF_BX) + i] = bx[(l*4 + gi + 1)*128 + k];
    }
    if (tid < 256) smf[F(OFF_BD) + tid] = bd[tid];
    if (tid < 256) smf[F(OFF_WT) + tid] = Wt[tid];
    if (tid < 256) smf[F(OFF_BT) + tid] = bt[tid];
    if (tid < 128) smf[F(OFF_BP) + tid] = bp[tid];
    if (tid < ROWS) {
        const float* mp = hmask + (size_t)(b0 + tid) * Lh;
        float s = 0.0f;
        for (int t = 0; t < Lh; t++) s += mp[t];
        s = fminf(fmaxf(s, 1.0f), (float)Lh);
        lastArr[tid] = (int)s - 1;
    }
    __syncthreads();

    // per-lane state: idx = nt*4 + rr; row = g4 + (rr>>1)*8; k = 16w + nt*8 + c4*2 + (rr&1)
    float cS[2][8], hS[2][8];
    #pragma unroll
    for (int l = 0; l < 2; l++)
        #pragma unroll
        for (int i = 0; i < 8; i++) { cS[l][i] = 0.0f; hS[l][i] = 0.0f; }

    // ================= time loop =================
    for (int t = 0; t < Lh; t++) {
        {
            int r = tid >> 4, d = tid & 15;    // 256 = 16 x 16
            smf[F(OFF_HISTB) + r*16 + d] = history[((size_t)(b0 + r) * Lh + t) * Dh + d];
        }
        if (tid < ROWS)
            smf[F(OFF_MSK) + tid] = hmask[(size_t)(b0 + tid) * Lh + t];
        __syncthreads();

        if (tid < ROWS) {
            float dd = fmaxf(smf[F(OFF_HISTB) + tid*16 + 5], 0.0f);
            smf[F(OFF_DEC) + tid] = 1.0f / logf(2.718281828459045f + dd);
        }
        // x = hist @ Wp + bp ; 16 rows x 16 threads, 8 channels per thread
        {
            int row = tid >> 4;
            int kb  = (tid & 15) * 8;
            float acc[8];
            #pragma unroll
            for (int ii = 0; ii < 8; ii++) acc[ii] = smf[F(OFF_BP) + kb + ii];
            #pragma unroll
            for (int d = 0; d < Dh; d++) {
                float hv = smf[F(OFF_HISTB) + row*16 + d];
                #pragma unroll
                for (int ii = 0; ii < 8; ii++)
                    acc[ii] += hv * smf[F(OFF_WP) + d*128 + kb + ii];
            }
            #pragma unroll
            for (int ii = 0; ii < 4; ii++)
                *(uint32_t*)(sm + OFF_A0 + row*ASTR + (kb + 2*ii)*2) =
                    packh2(acc[2*ii], acc[2*ii+1]);
        }
        __syncthreads();

        #pragma unroll
        for (int l = 0; l < 2; l++) {
            const uint32_t aB = smb + (l ? OFF_A1 : OFF_A0);

            // ---- gate GEMM: M=16, per gate n-tiles {2w,2w+1}, K=256 ----
            float zC[3][8];
            #pragma unroll
            for (int gi = 0; gi < 3; gi++)
                #pragma unroll
                for (int i = 0; i < 8; i++) zC[gi][i] = 0.0f;

            const ull* gbW = g_gb + (size_t)l * GB_LSTRIDE + w*64 + lane*2;
            // prefetch kt=0 fragments (pairs)
            ulonglong2 wb0 = *(const ulonglong2*)(gbW);
            ulonglong2 wb1 = *(const ulonglong2*)(gbW + 512);
            ulonglong2 wb2 = *(const ulonglong2*)(gbW + 1024);
            #pragma unroll 4
            for (int kt = 0; kt < 16; kt++) {
                uint32_t a[4];
                ldm4(a, aB + lmA + kt*32);
                ulonglong2 w0 = wb0, w1 = wb1, w2 = wb2;
                if (kt < 15) {
                    const ull* nx = gbW + (kt + 1) * 1536;
                    wb0 = *(const ulonglong2*)(nx);
                    wb1 = *(const ulonglong2*)(nx + 512);
                    wb2 = *(const ulonglong2*)(nx + 1024);
                }
                mma16816(&zC[0][0], a, (uint32_t)w0.x, (uint32_t)(w0.x >> 32));
                mma16816(&zC[0][4], a, (uint32_t)w0.y, (uint32_t)(w0.y >> 32));
                mma16816(&zC[1][0], a, (uint32_t)w1.x, (uint32_t)(w1.x >> 32));
                mma16816(&zC[1][4], a, (uint32_t)w1.y, (uint32_t)(w1.y >> 32));
                mma16816(&zC[2][0], a, (uint32_t)w2.x, (uint32_t)(w2.x >> 32));
                mma16816(&zC[2][4], a, (uint32_t)w2.y, (uint32_t)(w2.y >> 32));
            }

            // ---- epilogue 1: gates -> h_tilde, write HT ----
            float ot[8], htl[8];
            #pragma unroll
            for (int nt = 0; nt < 2; nt++) {
                int i0 = nt*4;
                int kbase = (w << 4) + nt*8 + (c4 << 1);
                float hts[4];
                #pragma unroll
                for (int rr = 0; rr < 4; rr++) {
                    int idx = i0 + rr;
                    int k   = kbase + (rr & 1);
                    float zi = zC[0][idx] + smf[F(OFF_BX) + (l*3 + 0)*128 + k];
                    float zo = zC[1][idx] + smf[F(OFF_BX) + (l*3 + 1)*128 + k];
                    float zc = zC[2][idx] + smf[F(OFF_BX) + (l*3 + 2)*128 + k];
                    float it = sig_f(zi);
                    ot[idx]  = sig_f(zo);
                    htl[idx] = tanh_f(zc) + it;
                    hts[rr]  = htl[idx];
                }
                int row0 = g4, row1 = g4 + 8;
                *(uint32_t*)(sm + OFF_HT + row0*HSTR + kbase*2) = packh2(hts[0], hts[1]);
                *(uint32_t*)(sm + OFF_HT + row1*HSTR + kbase*2) = packh2(hts[2], hts[3]);
            }
            __syncthreads();

            // ---- Wd GEMM: M=16, n-tiles {2w,2w+1}, K=128 ----
            float zD[8];
            #pragma unroll
            for (int i = 0; i < 8; i++) zD[i] = 0.0f;
            const ull* wbW = g_wb + (size_t)l * WB_LSTRIDE + w*64 + lane*2;
            ulonglong2 wd = *(const ulonglong2*)(wbW);
            #pragma unroll 4
            for (int kt = 0; kt < 8; kt++) {
                uint32_t hfr[4];
                ldm4(hfr, smb + OFF_HT + lmH + kt*32);
                ulonglong2 wv = wd;
                if (kt < 7) wd = *(const ulonglong2*)(wbW + (kt + 1) * 512);
                mma16816(&zD[0], hfr, (uint32_t)wv.x, (uint32_t)(wv.x >> 32));
                mma16816(&zD[4], hfr, (uint32_t)wv.y, (uint32_t)(wv.y >> 32));
            }

            // ---- epilogue 2: recurrence, state update, write h operand ----
            float dec2[2], msk2[2];
            int lst2[2];
            #pragma unroll
            for (int q = 0; q < 2; q++) {
                int row = g4 + q*8;
                dec2[q] = smf[F(OFF_DEC) + row];
                msk2[q] = smf[F(OFF_MSK) + row];
                lst2[q] = lastArr[row];
            }
            #pragma unroll
            for (int nt = 0; nt < 2; nt++) {
                int i0 = nt*4;
                int kbase = (w << 4) + nt*8 + (c4 << 1);
                float hvv[4];
                #pragma unroll
                for (int rr = 0; rr < 4; rr++) {
                    int idx = i0 + rr;
                    int q   = rr >> 1;
                    int k   = kbase + (rr & 1);
                    float hs    = tanh_f(zD[idx] + smf[F(OFF_BD) + l*128 + k]);
                    float dt    = sig_f(dec2[q] * smf[F(OFF_WT) + l*128 + k]
                                        + smf[F(OFF_BT) + l*128 + k]);
                    float hstar = (htl[idx] - hs) + hs * dt;
                    float cold  = cS[l][idx];
                    float cn    = tanh_f(hstar + ot[idx] * cold);
                    float hn    = ot[idx] * tanh_f(cn);
                    float m     = msk2[q];
                    float hv    = m * hn + (1.0f - m) * hS[l][idx];
                    float cv    = m * cn + (1.0f - m) * cold;
                    cS[l][idx] = cv;
                    hS[l][idx] = hv;
                    hvv[rr] = hv;
                    if (l == 1 && t == lst2[q])
                        smf[F(OFF_SV) + (g4 + q*8)*128 + k] = m * hv;
                }
                uint32_t p01 = packh2(hvv[0], hvv[1]);
                uint32_t p23 = packh2(hvv[2], hvv[3]);
                int row0 = g4, row1 = g4 + 8;
                if (l == 0) {
                    *(uint32_t*)(sm + OFF_A1 + row0*ASTR + kbase*2) = p01;
                    *(uint32_t*)(sm + OFF_A1 + row1*ASTR + kbase*2) = p23;
                    *(uint32_t*)(sm + OFF_A0 + row0*ASTR + 256 + kbase*2) = p01;
                    *(uint32_t*)(sm + OFF_A0 + row1*ASTR + 256 + kbase*2) = p23;
                } else {
                    *(uint32_t*)(sm + OFF_A1 + row0*ASTR + 256 + kbase*2) = p01;
                    *(uint32_t*)(sm + OFF_A1 + row1*ASTR + 256 + kbase*2) = p23;
                }
            }
            __syncthreads();
        }
    }

    // ================= forecast head =================
    {
        int r = tid >> 4, d = tid & 15;
        smf[F(OFF_HISTB) + r*16 + d] =
            history[((size_t)(b0 + r) * Lh + lastArr[r]) * Dh + d];
    }
    __syncthreads();

    const unsigned FULL = 0xffffffffu;
    #pragma unroll
    for (int rr = 0; rr < 2; rr++) {
        const int r = w * 2 + rr;

        float s = 0.0f, s2 = 0.0f;
        for (int i = lane; i < HEAD_IN; i += 32) {
            float v = (i < 16) ? smf[F(OFF_HISTB) + r*16 + i]
                               : smf[F(OFF_SV) + r*128 + (i - 16)];
            s += v; s2 += v * v;
        }
        #pragma unroll
        for (int off = 16; off; off >>= 1) {
            s  += __shfl_xor_sync(FULL, s,  off);
            s2 += __shfl_xor_sync(FULL, s2, off);
        }
        float mean = s / (float)HEAD_IN;
        float var  = s2 / (float)HEAD_IN - mean * mean;
        float rstd = rsqrtf(var + 1e-5f);

        const int j0 = lane * 4;
        float4 acc = *reinterpret_cast<const float4*>(b1 + j0);
        for (int i = 0; i < HEAD_IN; i++) {
            float v  = (i < 16) ? smf[F(OFF_HISTB) + r*16 + i]
                                : smf[F(OFF_SV) + r*128 + (i - 16)];
            float sn = (v - mean) * rstd * ln_g[i] + ln_b[i];
            float4 w4 = *reinterpret_cast<const float4*>(W1 + i * Hh + j0);
            acc.x += sn * w4.x; acc.y += sn * w4.y;
            acc.z += sn * w4.z; acc.w += sn * w4.w;
        }
        float y[4] = { fmaxf(acc.x, 0.0f), fmaxf(acc.y, 0.0f),
                       fmaxf(acc.z, 0.0f), fmaxf(acc.w, 0.0f) };

        const int o0 = lane, o1 = lane + 32;
        float a0 = b2[o0];
        float a1 = (o1 < OUTD) ? b2[o1] : 0.0f;
        #pragma unroll
        for (int q = 0; q < 4; q++) {
            float yq = y[q];
            #pragma unroll 8
            for (int src = 0; src < 32; src++) {
                float v = __shfl_sync(FULL, yq, src);
                int   j = src * 4 + q;
                a0 += v * W2[j * OUTD + o0];
                if (o1 < OUTD) a1 += v * W2[j * OUTD + o1];
            }
        }
        size_t ob = (size_t)(b0 + r) * OUTD;
        out[ob + o0] = fixv(a0);
        if (o1 < OUTD) out[ob + o1] = fixv(a1);
    }
}

extern "C" void kernel_launch(void* const* d_in, const int* in_sizes, int n_in,
                              void* d_out, int out_size)
{
    const float* history = (const float*)d_in[0];
    const float* hmask   = (const float*)d_in[1];
    const float* Wp      = (const float*)d_in[2];
    const float* bp      = (const float*)d_in[3];
    const float* Wx      = (const float*)d_in[4];
    const float* bx      = (const float*)d_in[5];
    const float* Uh      = (const float*)d_in[6];
    const float* Wd      = (const float*)d_in[7];
    const float* bd      = (const float*)d_in[8];
    const float* Wt      = (const float*)d_in[9];
    const float* bt      = (const float*)d_in[10];
    const float* ln_g    = (const float*)d_in[11];
    const float* ln_b    = (const float*)d_in[12];
    const float* W1      = (const float*)d_in[13];
    const float* b1      = (const float*)d_in[14];
    const float* W2      = (const float*)d_in[15];
    const float* b2      = (const float*)d_in[16];

    pack_kernel<<<224, 256>>>(Wx, Uh, Wd);

    cudaFuncSetAttribute(tlstm_mma_kernel,
                         cudaFuncAttributeMaxDynamicSharedMemorySize, SMEM_TOTAL);
    tlstm_mma_kernel<<<CTAS, THREADS, SMEM_TOTAL>>>(
        history, hmask, Wp, bp, bx, bd, Wt, bt,
        ln_g, ln_b, W1, b1, W2, b2, (float*)d_out);
}

// round 17
// speedup vs baseline: 1.0259x; 1.0259x over previous
#include <cuda_runtime.h>
#include <cuda_fp16.h>
#include <math.h>
#include <stdint.h>

#define Lh    64
#define Dh    16
#define Hh    128
#define ROWS  32
#define THREADS 512
#define CTAS  128
#define HEAD_IN 144
#define OUTD  60

typedef unsigned long long ull;

// ---- SMEM layout (bytes). A images: 32 rows x 264 fp16 (stride 528B). HT: stride 272B.
#define OFF_A0    0
#define OFF_A1    16896
#define OFF_HT    33792
#define OFF_SV    42496
#define OFF_WP    58880
#define OFF_HISTB 67072
#define OFF_MSK   69120      // 2 buffers x 32 floats
#define OFF_DEC   69376      // 2 buffers x 32 floats
#define OFF_LAST  69632
#define OFF_BP    69760
#define SMEM_TOTAL 70272
#define F(off) ((off) >> 2)
#define ASTR 528
#define HSTR 272

// weight blobs, fp16, stored ONCE (R13 layout):
// gates: [l][kt(16)][gi(3)][w(16)][lane(32)] (strides: l 24576, kt 1536, gi 512, w 32)
__device__ ull g_gb[2*16*3*16*32];
// Wd: [l][kt(8)][w(16)][lane(32)] (strides: l 4096, kt 512, w 32)
__device__ ull g_wb[2*8*16*32];

__global__ void pack_kernel(const float* __restrict__ Wx,
                            const float* __restrict__ Uh,
                            const float* __restrict__ Wd)
{
    int idx = blockIdx.x * blockDim.x + threadIdx.x;
    if (idx < 49152) {
        int l  = idx / 24576;
        int r  = idx % 24576;
        int kt = r / 1536;  r %= 1536;
        int gi = r / 512;   r %= 512;
        int w  = r / 32;
        int lane = r % 32;
        int n  = w * 8 + (lane >> 2);
        int kb = kt * 16 + (lane & 3) * 2;
        ull outv = 0;
        #pragma unroll
        for (int e = 0; e < 4; e++) {
            int kk = kb + (e & 1) + (e >> 1) * 8;   // kb, kb+1, kb+8, kb+9
            float v = (kk < 128)
                ? Wx[((size_t)(l*4 + gi + 1) * 128 + kk) * 128 + n]
                : Uh[((size_t)(l*4 + gi + 1) * 128 + (kk - 128)) * 128 + n];
            __half hv = __float2half_rn(v);
            outv |= (ull)(*(unsigned short*)&hv) << (16 * e);
        }
        g_gb[idx] = outv;
    } else if (idx < 49152 + 8192) {
        int i2 = idx - 49152;
        int l  = i2 / 4096;
        int r  = i2 % 4096;
        int kt = r / 512;  r %= 512;
        int w  = r / 32;
        int lane = r % 32;
        int n  = w * 8 + (lane >> 2);
        int kb = kt * 16 + (lane & 3) * 2;
        ull outv = 0;
        #pragma unroll
        for (int e = 0; e < 4; e++) {
            int kk = kb + (e & 1) + (e >> 1) * 8;
            float v = Wd[((size_t)l * 128 + kk) * 128 + n];
            __half hv = __float2half_rn(v);
            outv |= (ull)(*(unsigned short*)&hv) << (16 * e);
        }
        g_wb[i2] = outv;
    }
}

__device__ __forceinline__ uint32_t smem_u32(const void* p) {
    uint32_t a;
    asm("{ .reg .u64 t; cvta.to.shared.u64 t, %1; cvt.u32.u64 %0, t; }" : "=r"(a) : "l"(p));
    return a;
}
__device__ __forceinline__ void ldm4(uint32_t* r, uint32_t addr) {
    asm volatile("ldmatrix.sync.aligned.m8n8.x4.shared.b16 {%0,%1,%2,%3}, [%4];"
        : "=r"(r[0]), "=r"(r[1]), "=r"(r[2]), "=r"(r[3]) : "r"(addr));
}
__device__ __forceinline__ void mma16816(float* c, const uint32_t* a, uint32_t b0, uint32_t b1) {
    asm volatile("mma.sync.aligned.m16n8k16.row.col.f32.f16.f16.f32 "
        "{%0,%1,%2,%3}, {%4,%5,%6,%7}, {%8,%9}, {%0,%1,%2,%3};"
        : "+f"(c[0]), "+f"(c[1]), "+f"(c[2]), "+f"(c[3])
        : "r"(a[0]), "r"(a[1]), "r"(a[2]), "r"(a[3]), "r"(b0), "r"(b1));
}
__device__ __forceinline__ uint32_t packh2(float x, float y) {
    __half2 h = __floats2half2_rn(x, y);
    return *(uint32_t*)&h;
}
__device__ __forceinline__ float2 unpackh2(uint32_t v) {
    __half2 h = *reinterpret_cast<__half2*>(&v);
    return __half22float2(h);
}
__device__ __forceinline__ float tanh_f(float x) {
    float r;
    asm("tanh.approx.f32 %0, %1;" : "=f"(r) : "f"(x));
    return r;
}
__device__ __forceinline__ float sig_f(float x) {
    return fmaf(0.5f, tanh_f(0.5f * x), 0.5f);
}
__device__ __forceinline__ float fixv(float x) {
    if (!(x == x)) return 0.0f;
    if (x > 1e38f) return 1e4f;
    if (x < -1e38f) return -1e4f;
    return x;
}

__global__ void __launch_bounds__(THREADS, 1)
tlstm_mma_kernel(const float* __restrict__ history, const float* __restrict__ hmask,
                 const float* __restrict__ Wp,  const float* __restrict__ bp,
                 const float* __restrict__ bx,  const float* __restrict__ bd,
                 const float* __restrict__ Wt,  const float* __restrict__ bt,
                 const float* __restrict__ ln_g, const float* __restrict__ ln_b,
                 const float* __restrict__ W1,  const float* __restrict__ b1,
                 const float* __restrict__ W2,  const float* __restrict__ b2,
                 float* __restrict__ out)
{
    extern __shared__ char sm[];
    float* smf = (float*)sm;
    int*   lastArr = (int*)(sm + OFF_LAST);
    const uint32_t smb = smem_u32(sm);

    const int tid  = threadIdx.x;
    const int b0   = blockIdx.x * ROWS;
    const int w    = tid >> 5;       // 16 warps: n-tile w (8 channels per gate), full M=32
    const int lane = tid & 31;
    const int g4   = lane >> 2;
    const int c4   = lane & 3;
    const int kbase = w * 8 + c4 * 2;   // this lane's 2 k-channels

    // ldmatrix per-lane byte offsets (two m-tiles)
    const int lm_row = (lane & 7) + ((lane >> 3) & 1) * 8;
    const int lm_k8  = ((lane >> 4) & 1) * 8;
    const int lmA0 = lm_row * ASTR + lm_k8 * 2;
    const int lmA1 = (lm_row + 16) * ASTR + lm_k8 * 2;
    const int lmH0 = lm_row * HSTR + lm_k8 * 2;
    const int lmH1 = (lm_row + 16) * HSTR + lm_k8 * 2;

    // ---- init ----
    for (int i = tid; i < 33792 / 4; i += THREADS)   // zero A0,A1 (initial h = 0)
        ((uint32_t*)sm)[i] = 0;
    for (int i = tid; i < Dh * Hh; i += THREADS)
        smf[F(OFF_WP) + i] = Wp[i];
    if (tid < 128) smf[F(OFF_BP) + tid] = bp[tid];
    if (tid < ROWS) {
        const float* mp = hmask + (size_t)(b0 + tid) * Lh;
        float s = 0.0f;
        for (int t = 0; t < Lh; t++) s += mp[t];
        s = fminf(fmaxf(s, 1.0f), (float)Lh);
        lastArr[tid] = (int)s - 1;
        // mask/dec for t=0 into buffer 0
        smf[F(OFF_MSK) + tid] = mp[0];
        float dd = fmaxf(history[((size_t)(b0 + tid) * Lh) * Dh + 5], 0.0f);
        smf[F(OFF_DEC) + tid] = 1.0f / logf(2.718281828459045f + dd);
    }
    {   // hist slice t=0
        int r = tid >> 4, d = tid & 15;
        smf[F(OFF_HISTB) + r*16 + d] = history[((size_t)(b0 + r) * Lh) * Dh + d];
    }
    __syncthreads();

    // ---- biases hoisted to registers (this lane's 2 k-channels, both layers) ----
    float bxi[2][2], bxo[2][2], bxc[2][2], bdl[2][2], wtl[2][2], btl[2][2];
    #pragma unroll
    for (int l = 0; l < 2; l++) {
        #pragma unroll
        for (int q = 0; q < 2; q++) {
            int k = kbase + q;
            bxi[l][q] = bx[(l*4+1)*Hh + k];
            bxo[l][q] = bx[(l*4+2)*Hh + k];
            bxc[l][q] = bx[(l*4+3)*Hh + k];
            bdl[l][q] = bd[l*Hh + k];
            wtl[l][q] = Wt[l*Hh + k];
            btl[l][q] = bt[l*Hh + k];
        }
    }

    // x_0 GEMV -> A0 x-half
    {
        int row = tid >> 4;
        int kb  = (tid & 15) * 8;
        float acc[8];
        #pragma unroll
        for (int ii = 0; ii < 8; ii++) acc[ii] = smf[F(OFF_BP) + kb + ii];
        #pragma unroll
        for (int d = 0; d < Dh; d++) {
            float hv = smf[F(OFF_HISTB) + row*16 + d];
            #pragma unroll
            for (int ii = 0; ii < 8; ii++)
                acc[ii] += hv * smf[F(OFF_WP) + d*128 + kb + ii];
        }
        #pragma unroll
        for (int ii = 0; ii < 4; ii++)
            *(uint32_t*)(sm + OFF_A0 + row*ASTR + (kb + 2*ii)*2) =
                packh2(acc[2*ii], acc[2*ii+1]);
    }
    __syncthreads();

    // per-lane cell state only (h read back from fp16 A-images)
    float cS[2][8];
    #pragma unroll
    for (int l = 0; l < 2; l++)
        #pragma unroll
        for (int i = 0; i < 8; i++) cS[l][i] = 0.0f;

    int lst4[4];
    #pragma unroll
    for (int q = 0; q < 4; q++) lst4[q] = lastArr[g4 + q*8];

    // ================= time loop (4 syncs/step) =================
    for (int t = 0; t < Lh; t++) {
        const int cur = t & 1;

        #pragma unroll
        for (int l = 0; l < 2; l++) {
            const uint32_t aB  = smb + (l ? OFF_A1 : OFF_A0);
            const int      aOf = l ? OFF_A1 : OFF_A0;

            // staging for t+1 folded into layer-1 section (ordered by syncD)
            if (l == 1 && t + 1 < Lh) {
                if (tid < ROWS) {
                    smf[F(OFF_MSK) + ((t+1)&1)*32 + tid] =
                        hmask[(size_t)(b0 + tid) * Lh + t + 1];
                    float dd = fmaxf(history[((size_t)(b0 + tid) * Lh + t + 1) * Dh + 5], 0.0f);
                    smf[F(OFF_DEC) + ((t+1)&1)*32 + tid] =
                        1.0f / logf(2.718281828459045f + dd);
                }
                int r = tid >> 4, d = tid & 15;
                smf[F(OFF_HISTB) + r*16 + d] =
                    history[((size_t)(b0 + r) * Lh + t + 1) * Dh + d];
            }

            // ---- gate GEMM: M=32, n-tile w per gate, K=256 ----
            float zC[3][8];
            #pragma unroll
            for (int gi = 0; gi < 3; gi++)
                #pragma unroll
                for (int i = 0; i < 8; i++) zC[gi][i] = 0.0f;

            const ull* gbW = g_gb + (size_t)l * 24576 + w*32 + lane;
            ull wb0 = gbW[0];
            ull wb1 = gbW[512];
            ull wb2 = gbW[1024];
            #pragma unroll 4
            for (int kt = 0; kt < 16; kt++) {
                uint32_t a0[4], a1[4];
                ldm4(a0, aB + lmA0 + kt*32);
                ldm4(a1, aB + lmA1 + kt*32);
                ull w0 = wb0, w1 = wb1, w2 = wb2;
                if (kt < 15) {
                    const ull* nx = gbW + (kt + 1) * 1536;
                    wb0 = nx[0]; wb1 = nx[512]; wb2 = nx[1024];
                }
                mma16816(&zC[0][0], a0, (uint32_t)w0, (uint32_t)(w0 >> 32));
                mma16816(&zC[0][4], a1, (uint32_t)w0, (uint32_t)(w0 >> 32));
                mma16816(&zC[1][0], a0, (uint32_t)w1, (uint32_t)(w1 >> 32));
                mma16816(&zC[1][4], a1, (uint32_t)w1, (uint32_t)(w1 >> 32));
                mma16816(&zC[2][0], a0, (uint32_t)w2, (uint32_t)(w2 >> 32));
                mma16816(&zC[2][4], a1, (uint32_t)w2, (uint32_t)(w2 >> 32));
            }

            // ---- epilogue 1: gates -> h_tilde, write HT ----
            float ot[8], htl[8];
            #pragma unroll
            for (int mt = 0; mt < 2; mt++) {
                float hts[4];
                #pragma unroll
                for (int rr = 0; rr < 4; rr++) {
                    int idx = mt*4 + rr;
                    int q   = rr & 1;
                    float zi = zC[0][idx] + bxi[l][q];
                    float zo = zC[1][idx] + bxo[l][q];
                    float zc = zC[2][idx] + bxc[l][q];
                    float it = sig_f(zi);
                    ot[idx]  = sig_f(zo);
                    htl[idx] = tanh_f(zc) + it;
                    hts[rr]  = htl[idx];
                }
                int row0 = g4 + mt*16, row1 = row0 + 8;
                *(uint32_t*)(sm + OFF_HT + row0*HSTR + kbase*2) = packh2(hts[0], hts[1]);
                *(uint32_t*)(sm + OFF_HT + row1*HSTR + kbase*2) = packh2(hts[2], hts[3]);
            }
            __syncthreads();

            // ---- Wd GEMM: M=32, n-tile w, K=128 ----
            float zD[8];
            #pragma unroll
            for (int i = 0; i < 8; i++) zD[i] = 0.0f;
            const ull* wbW = g_wb + (size_t)l * 4096 + w*32 + lane;
            ull wd = wbW[0];
            #pragma unroll 4
            for (int kt = 0; kt < 8; kt++) {
                uint32_t h0[4], h1[4];
                ldm4(h0, smb + OFF_HT + lmH0 + kt*32);
                ldm4(h1, smb + OFF_HT + lmH1 + kt*32);
                ull wv = wd;
                if (kt < 7) wd = wbW[(kt + 1) * 512];
                mma16816(&zD[0], h0, (uint32_t)wv, (uint32_t)(wv >> 32));
                mma16816(&zD[4], h1, (uint32_t)wv, (uint32_t)(wv >> 32));
            }

            // ---- epilogue 2: recurrence, state update, write h operand ----
            float dec4[4], msk4[4];
            #pragma unroll
            for (int q = 0; q < 4; q++) {
                dec4[q] = smf[F(OFF_DEC) + cur*32 + g4 + q*8];
                msk4[q] = smf[F(OFF_MSK) + cur*32 + g4 + q*8];
            }
            #pragma unroll
            for (int mt = 0; mt < 2; mt++) {
                int row0 = g4 + mt*16, row1 = row0 + 8;
                // previous h (fp16) from this lane's own A-image slots
                float2 hp0 = unpackh2(*(uint32_t*)(sm + aOf + row0*ASTR + 256 + kbase*2));
                float2 hp1 = unpackh2(*(uint32_t*)(sm + aOf + row1*ASTR + 256 + kbase*2));
                float hvv[4];
                #pragma unroll
                for (int rr = 0; rr < 4; rr++) {
                    int idx = mt*4 + rr;
                    int q   = mt*2 + (rr >> 1);
                    int bq  = rr & 1;
                    float hprev = (rr < 2) ? (bq ? hp0.y : hp0.x) : (bq ? hp1.y : hp1.x);
                    float hs    = tanh_f(zD[idx] + bdl[l][bq]);
                    float dt    = sig_f(dec4[q] * wtl[l][bq] + btl[l][bq]);
                    float hstar = (htl[idx] - hs) + hs * dt;
                    float cold  = cS[l][idx];
                    float cn    = tanh_f(hstar + ot[idx] * cold);
                    float hn    = ot[idx] * tanh_f(cn);
                    float m     = msk4[q];
                    float hv    = m * hn + (1.0f - m) * hprev;
                    float cv    = m * cn + (1.0f - m) * cold;
                    cS[l][idx] = cv;
                    hvv[rr] = hv;
                    if (l == 1 && t == lst4[q])
                        smf[F(OFF_SV) + (g4 + q*8)*128 + kbase + bq] = m * hv;
                }
                uint32_t p01 = packh2(hvv[0], hvv[1]);
                uint32_t p23 = packh2(hvv[2], hvv[3]);
                if (l == 0) {
                    *(uint32_t*)(sm + OFF_A1 + row0*ASTR + kbase*2) = p01;
                    *(uint32_t*)(sm + OFF_A1 + row1*ASTR + kbase*2) = p23;
                    *(uint32_t*)(sm + OFF_A0 + row0*ASTR + 256 + kbase*2) = p01;
                    *(uint32_t*)(sm + OFF_A0 + row1*ASTR + 256 + kbase*2) = p23;
                } else {
                    *(uint32_t*)(sm + OFF_A1 + row0*ASTR + 256 + kbase*2) = p01;
                    *(uint32_t*)(sm + OFF_A1 + row1*ASTR + 256 + kbase*2) = p23;
                }
            }

            // x GEMV for t+1 folded into layer-1 epilogue (before the closing sync)
            if (l == 1 && t + 1 < Lh) {
                int row = tid >> 4;
                int kb  = (tid & 15) * 8;
                float acc[8];
                #pragma unroll
                for (int ii = 0; ii < 8; ii++) acc[ii] = smf[F(OFF_BP) + kb + ii];
                #pragma unroll
                for (int d = 0; d < Dh; d++) {
                    float hv = smf[F(OFF_HISTB) + row*16 + d];
                    #pragma unroll
                    for (int ii = 0; ii < 8; ii++)
                        acc[ii] += hv * smf[F(OFF_WP) + d*128 + kb + ii];
                }
                #pragma unroll
                for (int ii = 0; ii < 4; ii++)
                    *(uint32_t*)(sm + OFF_A0 + row*ASTR + (kb + 2*ii)*2) =
                        packh2(acc[2*ii], acc[2*ii+1]);
            }
            __syncthreads();
        }
    }

    // ================= forecast head =================
    {
        int r = tid >> 4, d = tid & 15;
        smf[F(OFF_HISTB) + r*16 + d] =
            history[((size_t)(b0 + r) * Lh + lastArr[r]) * Dh + d];
    }
    __syncthreads();

    const unsigned FULL = 0xffffffffu;
    #pragma unroll
    for (int rr = 0; rr < 2; rr++) {
        const int r = w * 2 + rr;

        float s = 0.0f, s2 = 0.0f;
        for (int i = lane; i < HEAD_IN; i += 32) {
            float v = (i < 16) ? smf[F(OFF_HISTB) + r*16 + i]
                               : smf[F(OFF_SV) + r*128 + (i - 16)];
            s += v; s2 += v * v;
        }
        #pragma unroll
        for (int off = 16; off; off >>= 1) {
            s  += __shfl_xor_sync(FULL, s,  off);
            s2 += __shfl_xor_sync(FULL, s2, off);
        }
        float mean = s / (float)HEAD_IN;
        float var  = s2 / (float)HEAD_IN - mean * mean;
        float rstd = rsqrtf(var + 1e-5f);

        const int j0 = lane * 4;
        float4 acc = *reinterpret_cast<const float4*>(b1 + j0);
        for (int i = 0; i < HEAD_IN; i++) {
            float v  = (i < 16) ? smf[F(OFF_HISTB) + r*16 + i]
                                : smf[F(OFF_SV) + r*128 + (i - 16)];
            float sn = (v - mean) * rstd * ln_g[i] + ln_b[i];
            float4 w4 = *reinterpret_cast<const float4*>(W1 + i * Hh + j0);
            acc.x += sn * w4.x; acc.y += sn * w4.y;
            acc.z += sn * w4.z; acc.w += sn * w4.w;
        }
        float y[4] = { fmaxf(acc.x, 0.0f), fmaxf(acc.y, 0.0f),
                       fmaxf(acc.z, 0.0f), fmaxf(acc.w, 0.0f) };

        const int o0 = lane, o1 = lane + 32;
        float a0 = b2[o0];
        float a1 = (o1 < OUTD) ? b2[o1] : 0.0f;
        #pragma unroll
        for (int q = 0; q < 4; q++) {
            float yq = y[q];
            #pragma unroll 8
            for (int src = 0; src < 32; src++) {
                float v = __shfl_sync(FULL, yq, src);
                int   j = src * 4 + q;
                a0 += v * W2[j * OUTD + o0];
                if (o1 < OUTD) a1 += v * W2[j * OUTD + o1];
            }
        }
        size_t ob = (size_t)(b0 + r) * OUTD;
        out[ob + o0] = fixv(a0);
        if (o1 < OUTD) out[ob + o1] = fixv(a1);
    }
}

extern "C" void kernel_launch(void* const* d_in, const int* in_sizes, int n_in,
                              void* d_out, int out_size)
{
    const float* history = (const float*)d_in[0];
    const float* hmask   = (const float*)d_in[1];
    const float* Wp      = (const float*)d_in[2];
    const float* bp      = (const float*)d_in[3];
    const float* Wx      = (const float*)d_in[4];
    const float* bx      = (const float*)d_in[5];
    const float* Uh      = (const float*)d_in[6];
    const float* Wd      = (const float*)d_in[7];
    const float* bd      = (const float*)d_in[8];
    const float* Wt      = (const float*)d_in[9];
    const float* bt      = (const float*)d_in[10];
    const float* ln_g    = (const float*)d_in[11];
    const float* ln_b    = (const float*)d_in[12];
    const float* W1      = (const float*)d_in[13];
    const float* b1      = (const float*)d_in[14];
    const float* W2      = (const float*)d_in[15];
    const float* b2      = (const float*)d_in[16];

    pack_kernel<<<225, 256>>>(Wx, Uh, Wd);

    cudaFuncSetAttribute(tlstm_mma_kernel,
                         cudaFuncAttributeMaxDynamicSharedMemorySize, SMEM_TOTAL);
    tlstm_mma_kernel<<<CTAS, THREADS, SMEM_TOTAL>>>(
        history, hmask, Wp, bp, bx, bd, Wt, bt,
        ln_g, ln_b, W1, b1, W2, b2, (float*)d_out);
}